// round 7
// baseline (speedup 1.0000x reference)
#include <cuda_runtime.h>
#include <math.h>
#include <stdint.h>

// Problem constants (fixed by setup_inputs)
#define HH 512
#define WW 512
#define HW (HH * WW)            // 262144
#define VV 64
#define V3 (VV * VV * VV)       // 262144

// Reachability: d>0 && in-range forces cz = rint((d+2)*15.75) in [32,63].
// Per-batch scratch: [((cx*64+cy)*32 + (cz-32))] float4{count,r,g,b} = 2 MB.
#define SCR_PER_B (VV * VV * 32)    // 131072 entries

// Pipeline: 32 batches as NG groups of GB, double-buffered scratch, with
// BLOCK SPECIALIZATION: NS producer blocks splat, NF consumer blocks
// finalize, running concurrently so DRAM reads and writes overlap.
#define GB 4
#define NG 8
#define GRP_SCR (GB * SCR_PER_B)        // 524288 entries = 8 MB per buffer
#define NBLK 148
#define NTHR 1024
#define NS 72                            // splat (producer) blocks
#define NF (NBLK - NS)                   // finalize (consumer) blocks = 76
#define QUADS_PER_GRP (GB * (HW / 4))    // 262144

__device__ __align__(128) float4 g_acc[2 * GRP_SCR];  // 16 MB; zero at load,
                                                      // finalize re-zeros.
__device__ unsigned g_splat_done[NG];                 // reset at kernel end
__device__ unsigned g_fin_done[NG];

// ---- policies / cache-op helpers -----------------------------------------
__device__ __forceinline__ uint64_t pol_evict_first() {
    uint64_t p;
    asm("createpolicy.fractional.L2::evict_first.b64 %0, 1.0;" : "=l"(p));
    return p;
}
__device__ __forceinline__ float4 ldg_stream(const float* a, uint64_t pol) {
    float4 v;
    asm("ld.global.nc.L2::cache_hint.v4.f32 {%0,%1,%2,%3}, [%4], %5;"
        : "=f"(v.x), "=f"(v.y), "=f"(v.z), "=f"(v.w) : "l"(a), "l"(pol));
    return v;
}
__device__ __forceinline__ void stg_stream(float* a, float4 v, uint64_t pol) {
    asm volatile("st.global.L2::cache_hint.v4.f32 [%0], {%1,%2,%3,%4}, %5;"
                 :: "l"(a), "f"(v.x), "f"(v.y), "f"(v.z), "f"(v.w), "l"(pol)
                 : "memory");
}
// Scratch access bypasses L1 (.cg): cross-SM REDs update L2 only.
__device__ __forceinline__ float4 ldcg4(const float4* a) {
    float4 v;
    asm volatile("ld.global.cg.v4.f32 {%0,%1,%2,%3}, [%4];"
                 : "=f"(v.x), "=f"(v.y), "=f"(v.z), "=f"(v.w) : "l"(a));
    return v;
}
__device__ __forceinline__ void stcg4(float4* a, float4 v) {
    asm volatile("st.global.cg.v4.f32 [%0], {%1,%2,%3,%4};"
                 :: "l"(a), "f"(v.x), "f"(v.y), "f"(v.z), "f"(v.w) : "memory");
}
__device__ __forceinline__ unsigned ld_acq(const unsigned* p) {
    unsigned v;
    asm volatile("ld.acquire.gpu.global.u32 %0, [%1];" : "=r"(v) : "l"(p)
                 : "memory");
    return v;
}
__device__ __forceinline__ void spin_until(const unsigned* ctr, unsigned tgt) {
    while (ld_acq(ctr) < tgt) __nanosleep(64);
}

// Branch-free resolve: count==0 => sums exactly 0 => sum*rcp(max(count,1))==0.
__device__ __forceinline__ void resolve(float4 a, float& occ, float& r,
                                        float& g, float& b) {
    float inv;
    asm("rcp.approx.f32 %0, %1;" : "=f"(inv) : "f"(fmaxf(a.x, 1.0f)));
    occ = (a.x > 0.0f) ? 1.0f : 0.0f;
    r = a.y * inv;
    g = a.z * inv;
    b = a.w * inv;
}

__global__ void __launch_bounds__(NTHR, 1)
fused_kernel(const float* __restrict__ rgbd, float* __restrict__ out) {
    const int bid = blockIdx.x;
    const int tid = threadIdx.x;
    const uint64_t pfirst = pol_evict_first();

    if (bid < NS) {
        // ======================= PRODUCER: splat =======================
        const int gt = bid * NTHR + tid;
        for (int g = 0; g < NG; g++) {
            if (g >= 2) {   // buffer reuse: finalize(g-2) must be complete
                if (tid == 0) spin_until(&g_fin_done[g - 2], NF);
                __syncthreads();
            }
            float4* buf = &g_acc[(size_t)(g & 1) * GRP_SCR];

            for (int Q = gt; Q < QUADS_PER_GRP; Q += NS * NTHR) {
                int bl = Q >> 16;            // batch within group
                int p = (Q & 65535) << 2;    // pixel index (mult of 4)
                int h = p >> 9;
                int w0 = p & (WW - 1);
                const float* base = rgbd + (size_t)(g * GB + bl) * (4 * HW);

                float4 d4 = ldg_stream(base + 3 * HW + p, pfirst);
                float dv[4] = {d4.x, d4.y, d4.z, d4.w};
                int   lin[4];
                bool  valid[4];
                bool  any = false;
                float yb = (float)h - 256.0f;   // fx=fy=256, cx=cy=256

                #pragma unroll
                for (int k = 0; k < 4; k++) {
                    float d = dv[k];
                    bool ok = (d > 0.0f) && (d < 10.0f) && isfinite(d);
                    float x = ((float)(w0 + k) - 256.0f) * d * (1.0f / 256.0f);
                    float y = yb * d * (1.0f / 256.0f);
                    // rintf = round-half-even = jnp.round; 15.75 == 63/4
                    // exactly -> same single rounding as the reference.
                    float fx_ = rintf((x + 2.0f) * 15.75f);
                    float fy_ = rintf((y + 2.0f) * 15.75f);
                    float fz_ = rintf((d + 2.0f) * 15.75f);
                    ok = ok && (fx_ >= 0.0f) && (fx_ <= 63.0f)
                            && (fy_ >= 0.0f) && (fy_ <= 63.0f)
                            && (fz_ >= 32.0f) && (fz_ <= 63.0f);
                    valid[k] = ok;
                    any = any || ok;
                    int cx = (int)fx_, cy = (int)fy_, cz = (int)fz_;
                    lin[k] = bl * SCR_PER_B +
                             ((((cx << 6) | cy) << 5) | (cz - 32));
                }

                if (any) {
                    float4 r4 = ldg_stream(base + 0 * HW + p, pfirst);
                    float4 g4 = ldg_stream(base + 1 * HW + p, pfirst);
                    float4 b4 = ldg_stream(base + 2 * HW + p, pfirst);
                    float rv[4] = {r4.x, r4.y, r4.z, r4.w};
                    float gv[4] = {g4.x, g4.y, g4.z, g4.w};
                    float bv[4] = {b4.x, b4.y, b4.z, b4.w};
                    #pragma unroll
                    for (int k = 0; k < 4; k++) {
                        if (valid[k]) {
                            float* a = (float*)&buf[lin[k]];
                            asm volatile(
                                "red.global.add.v4.f32 [%0], {%1,%2,%3,%4};"
                                :: "l"(a), "f"(1.0f), "f"(rv[k]), "f"(gv[k]),
                                   "f"(bv[k]) : "memory");
                        }
                    }
                }
            }
            __threadfence();      // make REDs visible before the release add
            __syncthreads();
            if (tid == 0) atomicAdd(&g_splat_done[g], 1u);
        }
    } else {
        // ====================== CONSUMER: finalize ======================
        const int fb = bid - NS;
        const int gt = fb * NTHR + tid;
        for (int g = 0; g < NG; g++) {
            if (tid == 0) spin_until(&g_splat_done[g], NS);
            __syncthreads();
            float4* buf = &g_acc[(size_t)(g & 1) * GRP_SCR];
            float4 z = make_float4(0.f, 0.f, 0.f, 0.f);

            for (int S = gt; S < GRP_SCR / 4; S += NF * NTHR) {
                int s = S << 2;                   // 4 contiguous entries
                int bl = s >> 17;                 // batch within group
                int sl = s & (SCR_PER_B - 1);     // ((cx*64+cy)*32 + cz-32)

                float4 a0 = ldcg4(&buf[s + 0]);
                float4 a1 = ldcg4(&buf[s + 1]);
                float4 a2 = ldcg4(&buf[s + 2]);
                float4 a3 = ldcg4(&buf[s + 3]);
                // rezero for reuse two groups later (stays dirty in L2)
                stcg4(&buf[s + 0], z); stcg4(&buf[s + 1], z);
                stcg4(&buf[s + 2], z); stcg4(&buf[s + 3], z);

                float4 occ, rr, gg, bb;
                resolve(a0, occ.x, rr.x, gg.x, bb.x);
                resolve(a1, occ.y, rr.y, gg.y, bb.y);
                resolve(a2, occ.z, rr.z, gg.z, bb.z);
                resolve(a3, occ.w, rr.w, gg.w, bb.w);

                int rhi = (sl >> 5) << 6;         // (cx*64+cy)*64
                int rocc = rhi + (sl & 31) + 32;  // occupied half
                int rzer = rhi + (sl & 31);       // zero half
                float* ob = out + (size_t)(g * GB + bl) * (4 * V3);

                stg_stream(ob + rocc,          occ, pfirst);
                stg_stream(ob + V3 + rocc,     rr,  pfirst);
                stg_stream(ob + 2 * V3 + rocc, gg,  pfirst);
                stg_stream(ob + 3 * V3 + rocc, bb,  pfirst);
                stg_stream(ob + rzer,          z, pfirst);
                stg_stream(ob + V3 + rzer,     z, pfirst);
                stg_stream(ob + 2 * V3 + rzer, z, pfirst);
                stg_stream(ob + 3 * V3 + rzer, z, pfirst);
            }
            __threadfence();      // rezero + output visible before release
            __syncthreads();
            if (tid == 0) atomicAdd(&g_fin_done[g], 1u);
        }

        // ---- counter reset for next graph replay (one consumer block) ----
        if (fb == 0) {
            if (tid == 0) spin_until(&g_fin_done[NG - 1], NF);
            __syncthreads();
            if (tid < NG) {
                g_splat_done[tid] = 0;
                g_fin_done[tid] = 0;
            }
            __threadfence();
        }
    }
}

extern "C" void kernel_launch(void* const* d_in, const int* in_sizes, int n_in,
                              void* d_out, int out_size) {
    const float* rgbd = (const float*)d_in[0];
    float* out = (float*)d_out;
    fused_kernel<<<NBLK, NTHR>>>(rgbd, out);
}

// round 8
// speedup vs baseline: 1.5368x; 1.5368x over previous
#include <cuda_runtime.h>
#include <math.h>
#include <stdint.h>

// Problem constants (fixed by setup_inputs)
#define HH 512
#define WW 512
#define HW (HH * WW)            // 262144
#define VV 64
#define V3 (VV * VV * VV)       // 262144
#define NB 32                   // batches

// Reachability: d>0 && in-range forces cz = rint((d+2)*15.75) in [32,63].
// Per-batch scratch: [((cx*64+cy)*32 + (cz-32))] float4{count,r,g,b} = 2 MB.
#define SCR_PER_B (VV * VV * 32)    // 131072 entries

// Two independent halves (batches 0..15 | 16..31), run as two parallel graph
// branches so one half's finalize (DRAM writes) overlaps the other half's
// splat (DRAM reads). 32 MB scratch per half, 64 MB total.
#define BHALF 16
#define HSCR (BHALF * SCR_PER_B)    // 2097152 entries = 32 MB per half
#define HPIX (BHALF * HW)           // 4194304 pixels per half

__device__ __align__(128) float4 g_acc[2 * HSCR];   // zero at load; per call:
                                                    // zero -> RED -> discard

// ---- policies / cache-op helpers -----------------------------------------
__device__ __forceinline__ uint64_t pol_evict_first() {
    uint64_t p;
    asm("createpolicy.fractional.L2::evict_first.b64 %0, 1.0;" : "=l"(p));
    return p;
}
__device__ __forceinline__ float4 ldg_stream(const float* a, uint64_t pol) {
    float4 v;
    asm("ld.global.nc.L2::cache_hint.v4.f32 {%0,%1,%2,%3}, [%4], %5;"
        : "=f"(v.x), "=f"(v.y), "=f"(v.z), "=f"(v.w) : "l"(a), "l"(pol));
    return v;
}
__device__ __forceinline__ void stg_stream(float* a, float4 v, uint64_t pol) {
    asm volatile("st.global.L2::cache_hint.v4.f32 [%0], {%1,%2,%3,%4}, %5;"
                 :: "l"(a), "f"(v.x), "f"(v.y), "f"(v.z), "f"(v.w), "l"(pol)
                 : "memory");
}

// ---------------------------------------------------------------- zero ----
// 128B (one L2 line) per thread: fills half-scratch with dirty zeros in L2.
__global__ __launch_bounds__(256) void zero_kernel(int half) {
    int t = blockIdx.x * blockDim.x + threadIdx.x;
    int s = (t << 3);
    if (s >= HSCR) return;
    float4* buf = &g_acc[(size_t)half * HSCR];
    float4 z = make_float4(0.f, 0.f, 0.f, 0.f);
    #pragma unroll
    for (int k = 0; k < 8; k++) buf[s + k] = z;
}

// --------------------------------------------------------------- splat ----
__global__ __launch_bounds__(256) void splat_kernel(
        const float* __restrict__ rgbd, int half) {
    int t = blockIdx.x * blockDim.x + threadIdx.x;
    if (t >= HPIX / 4) return;
    uint64_t pfirst = pol_evict_first();

    int idx = t << 2;                // first of 4 consecutive pixels (local)
    int bl = idx >> 18;              // batch within half (0..15)
    int p = idx & (HW - 1);          // pixel in image (mult of 4)
    int h = p >> 9;
    int w0 = p & (WW - 1);

    const float* base = rgbd + (size_t)(half * BHALF + bl) * (4 * HW);
    float4* buf = &g_acc[(size_t)half * HSCR];
    float4 d4 = ldg_stream(base + 3 * HW + p, pfirst);

    float dv[4] = {d4.x, d4.y, d4.z, d4.w};
    int   lin[4];
    bool  valid[4];
    bool  any = false;
    float yb = (float)h - 256.0f;    // fx=fy=256, cx=cy=256

    #pragma unroll
    for (int k = 0; k < 4; k++) {
        float d = dv[k];
        bool ok = (d > 0.0f) && (d < 10.0f) && isfinite(d);
        float x = ((float)(w0 + k) - 256.0f) * d * (1.0f / 256.0f);
        float y = yb * d * (1.0f / 256.0f);
        // rintf = round-half-even = jnp.round; 15.75 == 63/4 exactly, same
        // single rounding as ((p+2)/4)*63 in the reference.
        float fx_ = rintf((x + 2.0f) * 15.75f);
        float fy_ = rintf((y + 2.0f) * 15.75f);
        float fz_ = rintf((d + 2.0f) * 15.75f);
        ok = ok && (fx_ >= 0.0f) && (fx_ <= 63.0f)
                && (fy_ >= 0.0f) && (fy_ <= 63.0f)
                && (fz_ >= 32.0f) && (fz_ <= 63.0f);
        valid[k] = ok;
        any = any || ok;
        int cx = (int)fx_, cy = (int)fy_, cz = (int)fz_;
        lin[k] = bl * SCR_PER_B + ((((cx << 6) | cy) << 5) | (cz - 32));
    }

    if (!any) return;

    float4 r4 = ldg_stream(base + 0 * HW + p, pfirst);
    float4 g4 = ldg_stream(base + 1 * HW + p, pfirst);
    float4 b4 = ldg_stream(base + 2 * HW + p, pfirst);
    float rv[4] = {r4.x, r4.y, r4.z, r4.w};
    float gv[4] = {g4.x, g4.y, g4.z, g4.w};
    float bv[4] = {b4.x, b4.y, b4.z, b4.w};

    #pragma unroll
    for (int k = 0; k < 4; k++) {
        if (valid[k]) {
            float* a = (float*)&buf[lin[k]];
            asm volatile("red.global.add.v4.f32 [%0], {%1,%2,%3,%4};"
                         :: "l"(a), "f"(1.0f), "f"(rv[k]), "f"(gv[k]),
                            "f"(bv[k]) : "memory");
        }
    }
}

// ------------------------------------------------------------ finalize ----
// Branch-free resolve: count==0 => sums exactly 0 => sum*rcp(max(count,1))==0.
__device__ __forceinline__ void resolve(float4 a, float& occ, float& r,
                                        float& g, float& b) {
    float inv;
    asm("rcp.approx.f32 %0, %1;" : "=f"(inv) : "f"(fmaxf(a.x, 1.0f)));
    occ = (a.x > 0.0f) ? 1.0f : 0.0f;
    r = a.y * inv;
    g = a.z * inv;
    b = a.w * inv;
}

// Thread t owns ONE 128B scratch line = 8 entries; writes occupied + zero
// halves of the output, then discards its scratch line (no writeback).
__global__ __launch_bounds__(256) void finalize_kernel(
        float* __restrict__ out, int half) {
    int t = blockIdx.x * blockDim.x + threadIdx.x;
    if (t >= HSCR / 8) return;
    uint64_t pfirst = pol_evict_first();

    float4* buf = &g_acc[(size_t)half * HSCR];
    int s = t << 3;                    // 8 contiguous entries (one 128B line)
    int bl = s >> 17;                  // batch within half
    int sl = s & (SCR_PER_B - 1);      // ((cx*64+cy)*32 + (cz-32)), mult of 8

    float4 a[8];
    #pragma unroll
    for (int k = 0; k < 8; k++) a[k] = buf[s + k];

    float4 occ0, rr0, gg0, bb0, occ1, rr1, gg1, bb1;
    resolve(a[0], occ0.x, rr0.x, gg0.x, bb0.x);
    resolve(a[1], occ0.y, rr0.y, gg0.y, bb0.y);
    resolve(a[2], occ0.z, rr0.z, gg0.z, bb0.z);
    resolve(a[3], occ0.w, rr0.w, gg0.w, bb0.w);
    resolve(a[4], occ1.x, rr1.x, gg1.x, bb1.x);
    resolve(a[5], occ1.y, rr1.y, gg1.y, bb1.y);
    resolve(a[6], occ1.z, rr1.z, gg1.z, bb1.z);
    resolve(a[7], occ1.w, rr1.w, gg1.w, bb1.w);

    int rhi = (sl >> 5) << 6;          // (cx*64+cy)*64
    int rocc = rhi + (sl & 31) + 32;   // occupied half (cz>=32)
    int rzer = rhi + (sl & 31);        // zero half
    float* ob = out + (size_t)(half * BHALF + bl) * (4 * V3);
    float4 z = make_float4(0.f, 0.f, 0.f, 0.f);

    stg_stream(ob + rocc,              occ0, pfirst);
    stg_stream(ob + rocc + 4,          occ1, pfirst);
    stg_stream(ob + V3 + rocc,         rr0,  pfirst);
    stg_stream(ob + V3 + rocc + 4,     rr1,  pfirst);
    stg_stream(ob + 2 * V3 + rocc,     gg0,  pfirst);
    stg_stream(ob + 2 * V3 + rocc + 4, gg1,  pfirst);
    stg_stream(ob + 3 * V3 + rocc,     bb0,  pfirst);
    stg_stream(ob + 3 * V3 + rocc + 4, bb1,  pfirst);

    #pragma unroll
    for (int ch = 0; ch < 4; ch++) {
        stg_stream(ob + ch * V3 + rzer,     z, pfirst);
        stg_stream(ob + ch * V3 + rzer + 4, z, pfirst);
    }

    // Drop dirty scratch line without writeback; next call's zero_kernel
    // rewrites it. (Loads above are consumed by the stores -> safe.)
    asm volatile("discard.global.L2 [%0], 128;" :: "l"(&buf[s]) : "memory");
}

// ---------------------------------------------------------------------------
// Two parallel graph branches: default stream runs half 0, a side stream runs
// half 1 (forked/joined with events so capture sees proper dependencies).
// zeroB is ordered after zeroA purely by the fork point, phase-shifting the
// chains so finalize(A) [writes] overlaps splat(B) [reads].
static cudaStream_t g_side = nullptr;
static cudaEvent_t  g_fork = nullptr, g_join = nullptr;

extern "C" void kernel_launch(void* const* d_in, const int* in_sizes, int n_in,
                              void* d_out, int out_size) {
    const float* rgbd = (const float*)d_in[0];
    float* out = (float*)d_out;

    if (!g_side) {   // host-side objects only; created once, reused forever
        cudaStreamCreateWithFlags(&g_side, cudaStreamNonBlocking);
        cudaEventCreateWithFlags(&g_fork, cudaEventDisableTiming);
        cudaEventCreateWithFlags(&g_join, cudaEventDisableTiming);
    }

    const int T = 256;
    const int ZB = (HSCR / 8 + T - 1) / T;     // 1024 blocks
    const int SB = (HPIX / 4 + T - 1) / T;     // 4096 blocks
    const int FB = (HSCR / 8 + T - 1) / T;     // 1024 blocks

    // Chain A starts on the main (captured) stream.
    zero_kernel<<<ZB, T>>>(0);
    cudaEventRecord(g_fork, 0);
    cudaStreamWaitEvent(g_side, g_fork, 0);

    // Chain B on the side stream (begins after zeroA -> one-stage phase shift).
    zero_kernel<<<ZB, T, 0, g_side>>>(1);
    splat_kernel<<<SB, T, 0, g_side>>>(rgbd, 1);
    finalize_kernel<<<FB, T, 0, g_side>>>(out, 1);
    cudaEventRecord(g_join, g_side);

    // Chain A continues on the main stream, overlapping chain B.
    splat_kernel<<<SB, T>>>(rgbd, 0);
    finalize_kernel<<<FB, T>>>(out, 0);

    // Join the fork so the capture ends with a single terminal dependency.
    cudaStreamWaitEvent(0, g_join, 0);
}

// round 9
// speedup vs baseline: 1.5922x; 1.0361x over previous
#include <cuda_runtime.h>
#include <math.h>
#include <stdint.h>

// Problem constants (fixed by setup_inputs)
#define HH 512
#define WW 512
#define HW (HH * WW)            // 262144
#define VV 64
#define V3 (VV * VV * VV)       // 262144
#define NB 32
#define NPIX (NB * HW)          // 8388608

// Reachability: d>0 && in-range forces cz = rint((d+2)*15.75) in [32,63].
// Scratch: [b][((cx*64+cy)*32 + (cz-32))] float4{count,r,g,b}; 64 MB total.
// Lifecycle per call: zero_scratch dirties it in L2 (no DRAM read), splat
// REDs into L2, finalize reads + DISCARDs (no writeback) -> DRAM backing of
// the scratch stays zero forever.
#define SCR_PER_B (VV * VV * 32)     // 131072 (= 1<<17) entries per batch
#define NSCRATCH (NB * SCR_PER_B)    // 4194304 entries = 64 MB

// Output rows: out[b][ch][cx][cy][cz], 64 floats per row; floats [0,32) of
// every row are constant zeros (cz<32 unreachable) -> written by zero_out on
// an independent graph branch, overlapping splat's reads.
#define NROWS (NB * 4 * VV * VV)     // 524288 rows
#define ZSLOTS (NROWS * 8)           // 4194304 float4 zero-slots (64 MB)

__device__ __align__(128) float4 g_acc[NSCRATCH];

// ---- policies / cache-op helpers -----------------------------------------
__device__ __forceinline__ uint64_t pol_evict_first() {
    uint64_t p;
    asm("createpolicy.fractional.L2::evict_first.b64 %0, 1.0;" : "=l"(p));
    return p;
}
__device__ __forceinline__ float4 ldg_stream(const float* a, uint64_t pol) {
    float4 v;
    asm("ld.global.nc.L2::cache_hint.v4.f32 {%0,%1,%2,%3}, [%4], %5;"
        : "=f"(v.x), "=f"(v.y), "=f"(v.z), "=f"(v.w) : "l"(a), "l"(pol));
    return v;
}
__device__ __forceinline__ void stg_stream(float* a, float4 v, uint64_t pol) {
    asm volatile("st.global.L2::cache_hint.v4.f32 [%0], {%1,%2,%3,%4}, %5;"
                 :: "l"(a), "f"(v.x), "f"(v.y), "f"(v.z), "f"(v.w), "l"(pol)
                 : "memory");
}

// -------------------------------------------------------- zero scratch ----
// Warp-contiguous: block covers 2048 consecutive float4 (32 KB); store k of
// thread tid hits [blk*2048 + k*256 + tid] -> every STG is a full 512B
// warp-contiguous access.
__global__ __launch_bounds__(256) void zero_scratch_kernel() {
    int base = blockIdx.x * 2048 + threadIdx.x;
    float4 z = make_float4(0.f, 0.f, 0.f, 0.f);
    #pragma unroll
    for (int k = 0; k < 8; k++) g_acc[base + k * 256] = z;
}

// ------------------------------------------------- zero output (cz<32) ----
// Independent of everything: writes the constant-zero half of the output.
// Slot s -> row = s>>3, k = s&7, float4 at out + row*64 + k*4 (floats
// [0,32) of the row). Consecutive threads -> consecutive slots (coalesced).
__global__ __launch_bounds__(256) void zero_out_kernel(float* __restrict__ out) {
    int t = blockIdx.x * blockDim.x + threadIdx.x;   // 524288 threads
    uint64_t pfirst = pol_evict_first();
    float4 z = make_float4(0.f, 0.f, 0.f, 0.f);
    #pragma unroll
    for (int k = 0; k < 8; k++) {
        int s = t + k * 524288;
        int row = s >> 3;
        int kk = s & 7;
        stg_stream(out + (size_t)row * 64 + kk * 4, z, pfirst);
    }
}

// --------------------------------------------------------------- splat ----
__global__ __launch_bounds__(256) void splat_kernel(const float* __restrict__ rgbd) {
    int t = blockIdx.x * blockDim.x + threadIdx.x;
    if (t >= NPIX / 4) return;
    uint64_t pfirst = pol_evict_first();

    int idx = t << 2;                // first of 4 consecutive pixels
    int b = idx >> 18;               // / HW
    int p = idx & (HW - 1);          // % HW   (multiple of 4)
    int h = p >> 9;
    int w0 = p & (WW - 1);

    const float* base = rgbd + (size_t)b * (4 * HW);
    float4 d4 = ldg_stream(base + 3 * HW + p, pfirst);

    float dv[4] = {d4.x, d4.y, d4.z, d4.w};
    int   lin[4];
    bool  valid[4];
    bool  any = false;
    float yb = (float)h - 256.0f;    // fx=fy=256, cx=cy=256

    #pragma unroll
    for (int k = 0; k < 4; k++) {
        float d = dv[k];
        bool ok = (d > 0.0f) && (d < 10.0f) && isfinite(d);
        float x = ((float)(w0 + k) - 256.0f) * d * (1.0f / 256.0f);
        float y = yb * d * (1.0f / 256.0f);
        // rintf = round-half-even = jnp.round; 15.75 == 63/4 exactly, same
        // single rounding as ((p+2)/4)*63 in the reference.
        float fx_ = rintf((x + 2.0f) * 15.75f);
        float fy_ = rintf((y + 2.0f) * 15.75f);
        float fz_ = rintf((d + 2.0f) * 15.75f);
        ok = ok && (fx_ >= 0.0f) && (fx_ <= 63.0f)
                && (fy_ >= 0.0f) && (fy_ <= 63.0f)
                && (fz_ >= 32.0f) && (fz_ <= 63.0f);
        valid[k] = ok;
        any = any || ok;
        int cx = (int)fx_, cy = (int)fy_, cz = (int)fz_;
        lin[k] = (b << 17) + ((((cx << 6) | cy) << 5) | (cz - 32));
    }

    if (!any) return;

    float4 r4 = ldg_stream(base + 0 * HW + p, pfirst);
    float4 g4 = ldg_stream(base + 1 * HW + p, pfirst);
    float4 b4 = ldg_stream(base + 2 * HW + p, pfirst);
    float rv[4] = {r4.x, r4.y, r4.z, r4.w};
    float gv[4] = {g4.x, g4.y, g4.z, g4.w};
    float bv[4] = {b4.x, b4.y, b4.z, b4.w};

    #pragma unroll
    for (int k = 0; k < 4; k++) {
        if (valid[k]) {
            float* a = (float*)&g_acc[lin[k]];
            asm volatile("red.global.add.v4.f32 [%0], {%1,%2,%3,%4};"
                         :: "l"(a), "f"(1.0f), "f"(rv[k]), "f"(gv[k]),
                            "f"(bv[k]) : "memory");
        }
    }
}

// ------------------------------------------------------------ finalize ----
// Branch-free resolve: count==0 => sums exactly 0 => sum*rcp(max(count,1))==0.
__device__ __forceinline__ void resolve(float4 a, float& occ, float& r,
                                        float& g, float& b) {
    float inv;
    asm("rcp.approx.f32 %0, %1;" : "=f"(inv) : "f"(fmaxf(a.x, 1.0f)));
    occ = (a.x > 0.0f) ? 1.0f : 0.0f;
    r = a.y * inv;
    g = a.z * inv;
    b = a.w * inv;
}

// Occupied half (cz>=32) only; zero half is handled by zero_out_kernel.
// Thread t owns one 128B scratch line (8 entries), writes 8 float4 of
// output (full 128B lines per 4-thread group), then discards the line.
__global__ __launch_bounds__(256) void finalize_kernel(float* __restrict__ out) {
    int t = blockIdx.x * blockDim.x + threadIdx.x;
    if (t >= NSCRATCH / 8) return;
    uint64_t pfirst = pol_evict_first();

    int s = t << 3;                    // 8 contiguous entries (one 128B line)
    int b = s >> 17;                   // batch
    int sl = s & (SCR_PER_B - 1);      // ((cx*64+cy)*32 + (cz-32)), mult of 8

    float4 a[8];
    #pragma unroll
    for (int k = 0; k < 8; k++) a[k] = g_acc[s + k];

    float4 occ0, rr0, gg0, bb0, occ1, rr1, gg1, bb1;
    resolve(a[0], occ0.x, rr0.x, gg0.x, bb0.x);
    resolve(a[1], occ0.y, rr0.y, gg0.y, bb0.y);
    resolve(a[2], occ0.z, rr0.z, gg0.z, bb0.z);
    resolve(a[3], occ0.w, rr0.w, gg0.w, bb0.w);
    resolve(a[4], occ1.x, rr1.x, gg1.x, bb1.x);
    resolve(a[5], occ1.y, rr1.y, gg1.y, bb1.y);
    resolve(a[6], occ1.z, rr1.z, gg1.z, bb1.z);
    resolve(a[7], occ1.w, rr1.w, gg1.w, bb1.w);

    int rhi = (sl >> 5) << 6;          // (cx*64+cy)*64
    int rocc = rhi + (sl & 31) + 32;   // occupied half (16B aligned)
    float* ob = out + (size_t)b * (4 * V3);

    stg_stream(ob + rocc,              occ0, pfirst);
    stg_stream(ob + rocc + 4,          occ1, pfirst);
    stg_stream(ob + V3 + rocc,         rr0,  pfirst);
    stg_stream(ob + V3 + rocc + 4,     rr1,  pfirst);
    stg_stream(ob + 2 * V3 + rocc,     gg0,  pfirst);
    stg_stream(ob + 2 * V3 + rocc + 4, gg1,  pfirst);
    stg_stream(ob + 3 * V3 + rocc,     bb0,  pfirst);
    stg_stream(ob + 3 * V3 + rocc + 4, bb1,  pfirst);

    // Drop dirty scratch line without writeback (DRAM backing stays zero;
    // next call's zero_scratch redirties it in L2).
    asm volatile("discard.global.L2 [%0], 128;" :: "l"(&g_acc[s]) : "memory");
}

// ---------------------------------------------------------------------------
// Graph shape: root forks; branch B runs zero_out (constant half of output,
// depends on nothing) concurrently with branch A's zero_scratch -> splat ->
// finalize. zero_out's DRAM writes overlap splat's DRAM reads.
static cudaStream_t g_side = nullptr;
static cudaEvent_t  g_fork = nullptr, g_join = nullptr;

extern "C" void kernel_launch(void* const* d_in, const int* in_sizes, int n_in,
                              void* d_out, int out_size) {
    const float* rgbd = (const float*)d_in[0];
    float* out = (float*)d_out;

    if (!g_side) {   // host-side objects only; created once, reused forever
        cudaStreamCreateWithFlags(&g_side, cudaStreamNonBlocking);
        cudaEventCreateWithFlags(&g_fork, cudaEventDisableTiming);
        cudaEventCreateWithFlags(&g_join, cudaEventDisableTiming);
    }

    const int T = 256;

    // Fork at capture root.
    cudaEventRecord(g_fork, 0);
    cudaStreamWaitEvent(g_side, g_fork, 0);

    // Branch B (independent): constant-zero half of the output, 64 MB writes.
    zero_out_kernel<<<524288 / T, T, 0, g_side>>>(out);
    cudaEventRecord(g_join, g_side);

    // Branch A: scratch fill (L2) -> splat (128 MB reads) -> finalize (64 MB
    // occupied writes).
    zero_scratch_kernel<<<NSCRATCH / 2048, T>>>();
    splat_kernel<<<(NPIX / 4) / T, T>>>(rgbd);
    finalize_kernel<<<(NSCRATCH / 8) / T, T>>>(out);

    cudaStreamWaitEvent(0, g_join, 0);
}

// round 10
// speedup vs baseline: 1.6308x; 1.0242x over previous
#include <cuda_runtime.h>
#include <math.h>
#include <stdint.h>

// Problem constants (fixed by setup_inputs)
#define HH 512
#define WW 512
#define HW (HH * WW)            // 262144
#define VV 64
#define V3 (VV * VV * VV)       // 262144
#define NB 32
#define NPIX (NB * HW)          // 8388608

// Reachability: d>0 && in-range forces cz = rint((d+2)*15.75) in [32,63].
// Scratch: [b][((cx*64+cy)*32 + (cz-32))] float4{count,r,g,b}; 64 MB.
// Lifecycle per call: zero_scratch dirties it in L2 (no DRAM read), splat
// REDs into L2, finalize reads + DISCARDs (no writeback) -> scratch's DRAM
// backing stays zero forever.
#define SCR_PER_B (VV * VV * 32)     // 131072 (= 1<<17) entries per batch
#define NSCRATCH (NB * SCR_PER_B)    // 4194304 entries = 64 MB

__device__ __align__(128) float4 g_acc[NSCRATCH];

// ---- 256-bit memory helpers (sm_100+, PTX 8.7) ----------------------------
__device__ __forceinline__ void ldg256(const float* p, float4& v0, float4& v1) {
    asm volatile("ld.global.v8.f32 {%0,%1,%2,%3,%4,%5,%6,%7}, [%8];"
                 : "=f"(v0.x), "=f"(v0.y), "=f"(v0.z), "=f"(v0.w),
                   "=f"(v1.x), "=f"(v1.y), "=f"(v1.z), "=f"(v1.w)
                 : "l"(p));
}
__device__ __forceinline__ void stg256(float* p, float4 v0, float4 v1) {
    asm volatile("st.global.v8.f32 [%0], {%1,%2,%3,%4,%5,%6,%7,%8};"
                 :: "l"(p), "f"(v0.x), "f"(v0.y), "f"(v0.z), "f"(v0.w),
                    "f"(v1.x), "f"(v1.y), "f"(v1.z), "f"(v1.w)
                 : "memory");
}
// Streaming input loads keep the evict_first hint (proven in splat).
__device__ __forceinline__ uint64_t pol_evict_first() {
    uint64_t p;
    asm("createpolicy.fractional.L2::evict_first.b64 %0, 1.0;" : "=l"(p));
    return p;
}
__device__ __forceinline__ float4 ldg_stream(const float* a, uint64_t pol) {
    float4 v;
    asm("ld.global.nc.L2::cache_hint.v4.f32 {%0,%1,%2,%3}, [%4], %5;"
        : "=f"(v.x), "=f"(v.y), "=f"(v.z), "=f"(v.w) : "l"(a), "l"(pol));
    return v;
}

// -------------------------------------------------------- zero scratch ----
// One 128B L2 line per thread via 4 x STG.256 (contiguous per thread; warp
// covers 4KB contiguous).
__global__ __launch_bounds__(256) void zero_scratch_kernel() {
    int t = blockIdx.x * blockDim.x + threadIdx.x;   // NSCRATCH/8 threads
    float* p = (float*)&g_acc[(size_t)t << 3];
    float4 z = make_float4(0.f, 0.f, 0.f, 0.f);
    stg256(p,      z, z);
    stg256(p + 8,  z, z);
    stg256(p + 16, z, z);
    stg256(p + 24, z, z);
}

// --------------------------------------------------------------- splat ----
__global__ __launch_bounds__(256) void splat_kernel(const float* __restrict__ rgbd) {
    int t = blockIdx.x * blockDim.x + threadIdx.x;
    if (t >= NPIX / 4) return;
    uint64_t pfirst = pol_evict_first();

    int idx = t << 2;                // first of 4 consecutive pixels
    int b = idx >> 18;               // / HW
    int p = idx & (HW - 1);          // % HW   (multiple of 4)
    int h = p >> 9;
    int w0 = p & (WW - 1);

    const float* base = rgbd + (size_t)b * (4 * HW);
    float4 d4 = ldg_stream(base + 3 * HW + p, pfirst);

    float dv[4] = {d4.x, d4.y, d4.z, d4.w};
    int   lin[4];
    bool  valid[4];
    bool  any = false;
    float yb = (float)h - 256.0f;    // fx=fy=256, cx=cy=256

    #pragma unroll
    for (int k = 0; k < 4; k++) {
        float d = dv[k];
        bool ok = (d > 0.0f) && (d < 10.0f) && isfinite(d);
        float x = ((float)(w0 + k) - 256.0f) * d * (1.0f / 256.0f);
        float y = yb * d * (1.0f / 256.0f);
        // rintf = round-half-even = jnp.round; 15.75 == 63/4 exactly, same
        // single rounding as ((p+2)/4)*63 in the reference.
        float fx_ = rintf((x + 2.0f) * 15.75f);
        float fy_ = rintf((y + 2.0f) * 15.75f);
        float fz_ = rintf((d + 2.0f) * 15.75f);
        ok = ok && (fx_ >= 0.0f) && (fx_ <= 63.0f)
                && (fy_ >= 0.0f) && (fy_ <= 63.0f)
                && (fz_ >= 32.0f) && (fz_ <= 63.0f);
        valid[k] = ok;
        any = any || ok;
        int cx = (int)fx_, cy = (int)fy_, cz = (int)fz_;
        lin[k] = (b << 17) + ((((cx << 6) | cy) << 5) | (cz - 32));
    }

    if (!any) return;

    float4 r4 = ldg_stream(base + 0 * HW + p, pfirst);
    float4 g4 = ldg_stream(base + 1 * HW + p, pfirst);
    float4 b4 = ldg_stream(base + 2 * HW + p, pfirst);
    float rv[4] = {r4.x, r4.y, r4.z, r4.w};
    float gv[4] = {g4.x, g4.y, g4.z, g4.w};
    float bv[4] = {b4.x, b4.y, b4.z, b4.w};

    #pragma unroll
    for (int k = 0; k < 4; k++) {
        if (valid[k]) {
            float* a = (float*)&g_acc[lin[k]];
            asm volatile("red.global.add.v4.f32 [%0], {%1,%2,%3,%4};"
                         :: "l"(a), "f"(1.0f), "f"(rv[k]), "f"(gv[k]),
                            "f"(bv[k]) : "memory");
        }
    }
}

// ------------------------------------------------------------ finalize ----
// Branch-free resolve: count==0 => sums exactly 0 => sum*rcp(max(count,1))==0.
__device__ __forceinline__ void resolve(float4 a, float& occ, float& r,
                                        float& g, float& b) {
    float inv;
    asm("rcp.approx.f32 %0, %1;" : "=f"(inv) : "f"(fmaxf(a.x, 1.0f)));
    occ = (a.x > 0.0f) ? 1.0f : 0.0f;
    r = a.y * inv;
    g = a.z * inv;
    b = a.w * inv;
}

// Thread t owns ONE 128B scratch line (8 entries, 32B-aligned pairs):
// 4 x LDG.256 in, 4 x STG.256 occupied half + 4 x STG.256 zero half out,
// then one discard. Both output halves written here (measured faster than
// splitting the zero half into a separate kernel).
__global__ __launch_bounds__(256) void finalize_kernel(float* __restrict__ out) {
    int t = blockIdx.x * blockDim.x + threadIdx.x;
    if (t >= NSCRATCH / 8) return;

    int s = t << 3;                    // 8 contiguous entries (one 128B line)
    int b = s >> 17;                   // batch
    int sl = s & (SCR_PER_B - 1);      // ((cx*64+cy)*32 + (cz-32)), mult of 8

    const float* sp = (const float*)&g_acc[s];
    float4 a[8];
    ldg256(sp,      a[0], a[1]);
    ldg256(sp + 8,  a[2], a[3]);
    ldg256(sp + 16, a[4], a[5]);
    ldg256(sp + 24, a[6], a[7]);

    float4 occ0, rr0, gg0, bb0, occ1, rr1, gg1, bb1;
    resolve(a[0], occ0.x, rr0.x, gg0.x, bb0.x);
    resolve(a[1], occ0.y, rr0.y, gg0.y, bb0.y);
    resolve(a[2], occ0.z, rr0.z, gg0.z, bb0.z);
    resolve(a[3], occ0.w, rr0.w, gg0.w, bb0.w);
    resolve(a[4], occ1.x, rr1.x, gg1.x, bb1.x);
    resolve(a[5], occ1.y, rr1.y, gg1.y, bb1.y);
    resolve(a[6], occ1.z, rr1.z, gg1.z, bb1.z);
    resolve(a[7], occ1.w, rr1.w, gg1.w, bb1.w);

    int rhi = (sl >> 5) << 6;          // (cx*64+cy)*64
    int rocc = rhi + (sl & 31) + 32;   // occupied half (32B aligned)
    int rzer = rhi + (sl & 31);        // zero half (32B aligned)
    float* ob = out + (size_t)b * (4 * V3);
    float4 z = make_float4(0.f, 0.f, 0.f, 0.f);

    stg256(ob + rocc,          occ0, occ1);
    stg256(ob + V3 + rocc,     rr0,  rr1);
    stg256(ob + 2 * V3 + rocc, gg0,  gg1);
    stg256(ob + 3 * V3 + rocc, bb0,  bb1);

    stg256(ob + rzer,          z, z);
    stg256(ob + V3 + rzer,     z, z);
    stg256(ob + 2 * V3 + rzer, z, z);
    stg256(ob + 3 * V3 + rzer, z, z);

    // Drop the dirty scratch line without writeback (DRAM backing stays
    // zero; next call's zero_scratch redirties it in L2).
    asm volatile("discard.global.L2 [%0], 128;" :: "l"(&g_acc[s]) : "memory");
}

extern "C" void kernel_launch(void* const* d_in, const int* in_sizes, int n_in,
                              void* d_out, int out_size) {
    const float* rgbd = (const float*)d_in[0];
    float* out = (float*)d_out;

    const int T = 256;
    zero_scratch_kernel<<<(NSCRATCH / 8) / T, T>>>();
    splat_kernel<<<(NPIX / 4) / T, T>>>(rgbd);
    finalize_kernel<<<(NSCRATCH / 8) / T, T>>>(out);
}